// round 17
// baseline (speedup 1.0000x reference)
#include <cuda_runtime.h>
#include <cuda_bf16.h>

#define N_NODES 100000
#define N_EDGES 3200000
#define IN_C 5
#define OUT_C 64
#define HID_C 128
#define YSTRIDE 8              // 6 used channels + spare, 32B row = 1 sector
#define ADJ_W 96               // padded adjacency row width (max deg ~59 at 5.5σ)

#define FUSE_BS 512
#define FUSE_NB ((N_NODES + FUSE_BS - 1) / FUSE_BS)   // 196
#define BIN_NB (N_EDGES / 4 / 256)                    // 3125 (exact)

// ---------------------------------------------------------------------------
// Scratch (device globals; no allocation allowed)
// ---------------------------------------------------------------------------
__device__ int   g_cursor[N_NODES];                   // becomes deg after bin
__device__ float g_dinv[N_NODES];
__device__ int   g_adj[(size_t)N_NODES * ADJ_W];      // padded rows, 38.4 MB
__device__ float g_ys0[(N_NODES + 1) * YSTRIDE];      // dinv*[x | 1]; row N = 0
__device__ float g_ys1[(N_NODES + 1) * YSTRIDE];      // dinv*out1 (+ ch6 = Â1, ch7 = dinv)
__device__ float g_Wc[IN_C * OUT_C];                  // W1 @ W2  (5x64)
__device__ float g_bvec[OUT_C];                       // b1 @ W2

// ---------------------------------------------------------------------------
// K1 (fused count+bin): block 0 does the independent weight collapse +
// pad-row zeroing (overlapped with the edge sweep); blocks 1..BIN_NB do the
// edge pass: rank = cursor++; scatter src into padded row. 4 edges/thread.
// ---------------------------------------------------------------------------
__global__ __launch_bounds__(256) void k_bin(const int4* __restrict__ src4,
                                             const int4* __restrict__ dst4,
                                             const float* __restrict__ W1,
                                             const float* __restrict__ b1,
                                             const float* __restrict__ W2) {
    int t = threadIdx.x;
    if (blockIdx.x == 0) {
        // --- weight collapse (needs 384 lanes over 2 rounds of 256) ---
        for (int tt = t; tt < 384; tt += 256) {
            int c = tt >> 6;                 // 0..5
            int j = tt & 63;
            float s = 0.0f;
            if (c < IN_C) {
                for (int k = 0; k < HID_C; k++)
                    s += W1[c * HID_C + k] * W2[k * OUT_C + j];
                g_Wc[c * OUT_C + j] = s;
            } else {
                for (int k = 0; k < HID_C; k++)
                    s += b1[k] * W2[k * OUT_C + j];
                g_bvec[j] = s;
            }
        }
        if (t < 16) {                        // zero pad rows of ys0/ys1
            if (t < 8)  g_ys0[(size_t)N_NODES * YSTRIDE + t] = 0.f;
            else        g_ys1[(size_t)N_NODES * YSTRIDE + (t - 8)] = 0.f;
        }
        return;
    }

    int i = (blockIdx.x - 1) * 256 + t;      // exact: BIN_NB*256 == N_EDGES/4
    int4 s = __ldg(&src4[i]);
    int4 d = __ldg(&dst4[i]);
    int r0 = atomicAdd(&g_cursor[d.x], 1);
    int r1 = atomicAdd(&g_cursor[d.y], 1);
    int r2 = atomicAdd(&g_cursor[d.z], 1);
    int r3 = atomicAdd(&g_cursor[d.w], 1);
    // OOB clamp (deg > ADJ_W has probability ~1e-19; clamp keeps memory safe)
    if (r0 < ADJ_W) g_adj[(size_t)d.x * ADJ_W + r0] = s.x;
    if (r1 < ADJ_W) g_adj[(size_t)d.y * ADJ_W + r1] = s.y;
    if (r2 < ADJ_W) g_adj[(size_t)d.z * ADJ_W + r2] = s.z;
    if (r3 < ADJ_W) g_adj[(size_t)d.w * ADJ_W + r3] = s.w;
}

// ---------------------------------------------------------------------------
// K2: dinv from cursor(=deg), ys0 pack.
// ---------------------------------------------------------------------------
__global__ void k_fuse(const float* __restrict__ x) {
    int i = blockIdx.x * FUSE_BS + threadIdx.x;
    if (i >= N_NODES) return;
    int v = g_cursor[i];                     // in-degree
    float dn = rsqrtf((float)(v + 1));       // +1 self-loop
    g_dinv[i] = dn;
    const float* xr = x + (size_t)i * IN_C;
    float4* yr = (float4*)(g_ys0 + (size_t)i * YSTRIDE);
    yr[0] = make_float4(dn * xr[0], dn * xr[1], dn * xr[2], dn * xr[3]);
    yr[1] = make_float4(dn * xr[4], dn, 0.f, 0.f);
}

// ---------------------------------------------------------------------------
// Aggregation: FOUR NODES PER WARP (8-lane groups), 2 lanes per edge,
// SOFTWARE-PIPELINED: next iteration's adj index is loaded before the current
// feature gather, breaking the adj->feat serial chain.
// PASS 0: ys1[n] = dinv²(Σ+self) ch0-5; ch6 = (Â1)[n]; ch7 = dinv[n].
// PASS 1: out2 = dinv(Σ+self) ch0-4; fused 5->64 output projection.
// ---------------------------------------------------------------------------
template <int PASS>
__global__ __launch_bounds__(256) void k_agg(float* __restrict__ z,
                                             const float* __restrict__ b2) {
    const float* __restrict__ yin = (PASS == 0) ? g_ys0 : g_ys1;

    int warp = (blockIdx.x * blockDim.x + threadIdx.x) >> 5;   // 0..24999
    int lane = threadIdx.x & 31;
    int grp   = lane >> 3;                // 0..3
    int glane = lane & 7;                 // 0..7
    int n     = warp * 4 + grp;           // < N_NODES always (exact grid)

    int deg = __ldg(&g_cursor[n]);
    if (deg > ADJ_W) deg = ADJ_W;
    int m1   = max(deg, __shfl_xor_sync(0xffffffffu, deg, 8));
    int mdeg = max(m1,  __shfl_xor_sync(0xffffffffu, m1, 16));

    const int* row = g_adj + (size_t)n * ADJ_W;
    int half = glane >> 1;                // edge slot 0..3
    int part = glane & 1;                 // 0: ch0-3, 1: ch4-7

    float b0 = 0.f, b1v = 0.f, b2v = 0.f, b3 = 0.f;

    // prologue prefetch
    int s_cur = (half < deg) ? __ldg(&row[half]) : N_NODES;

    for (int base = 0; base < mdeg; base += 4) {
        int kn = base + 4 + half;
        int s_nxt = (base + 4 < mdeg)
                    ? ((kn < deg) ? __ldg(&row[kn]) : N_NODES)
                    : N_NODES;
        float4 v = __ldg((const float4*)(yin + (size_t)s_cur * YSTRIDE) + part);
        b0 += v.x;  b1v += v.y;  b2v += v.z;  b3 += v.w;
        s_cur = s_nxt;
    }

    // reduce across the 4 slots within this parity class (strides 4,2 stay
    // inside the 8-lane group and preserve parity)
#pragma unroll
    for (int o = 4; o >= 2; o >>= 1) {
        b0  += __shfl_xor_sync(0xffffffffu, b0,  o);
        b1v += __shfl_xor_sync(0xffffffffu, b1v, o);
        b2v += __shfl_xor_sync(0xffffffffu, b2v, o);
        b3  += __shfl_xor_sync(0xffffffffu, b3,  o);
    }
    // exchange with opposite parity
    float p0 = __shfl_xor_sync(0xffffffffu, b0,  1);
    float p1 = __shfl_xor_sync(0xffffffffu, b1v, 1);
    float p2 = __shfl_xor_sync(0xffffffffu, b2v, 1);
    float p3 = __shfl_xor_sync(0xffffffffu, b3,  1);

    float a0, a1, a2, a3, a4, a5;
    if (part == 0) { a0 = b0; a1 = b1v; a2 = b2v; a3 = b3; a4 = p0; a5 = p1; }
    else           { a0 = p0; a1 = p1;  a2 = p2;  a3 = p3; a4 = b0; a5 = b1v; }

    const float4* yr = (const float4*)(yin + (size_t)n * YSTRIDE);
    float4 s0 = __ldg(yr);                // self row (broadcast within group)
    float4 s1 = __ldg(yr + 1);

    if (PASS == 0) {
        float dn = s1.y;                  // ys0 ch5 == dinv[n]
        float o0 = dn * (a0 + s0.x);
        float o1 = dn * (a1 + s0.y);
        float o2 = dn * (a2 + s0.z);
        float o3 = dn * (a3 + s0.w);
        float o4 = dn * (a4 + s1.x);
        float o5 = dn * (a5 + s1.y);      // (Â1)[n], unscaled
        if (glane == 0) {
            float4* d4 = (float4*)(g_ys1 + (size_t)n * YSTRIDE);
            d4[0] = make_float4(dn * o0, dn * o1, dn * o2, dn * o3);
            d4[1] = make_float4(dn * o4, dn * o5, o5, dn);   // ch7 = dinv
        }
    } else {
        float dn = s1.w;                  // ys1 ch7 == dinv[n]
        float o0 = dn * (a0 + s0.x);
        float o1 = dn * (a1 + s0.y);
        float o2 = dn * (a2 + s0.z);
        float o3 = dn * (a3 + s0.w);
        float o4 = dn * (a4 + s1.x);
        float ab1 = s1.z;                 // (Â1)[n] stashed in channel 6
        float* zr = z + (size_t)n * OUT_C;
#pragma unroll
        for (int h = 0; h < 8; h++) {
            int j = glane + h * 8;
            float acc = __ldg(&b2[j]) + ab1 * g_bvec[j];
            acc += o0 * g_Wc[0 * OUT_C + j];
            acc += o1 * g_Wc[1 * OUT_C + j];
            acc += o2 * g_Wc[2 * OUT_C + j];
            acc += o3 * g_Wc[3 * OUT_C + j];
            acc += o4 * g_Wc[4 * OUT_C + j];
            zr[j] = acc;
        }
    }
}

// ---------------------------------------------------------------------------
// Launch. Inputs (metadata order): x, edge_index, W1, b1, W2, b2.
// ---------------------------------------------------------------------------
extern "C" void kernel_launch(void* const* d_in, const int* in_sizes, int n_in,
                              void* d_out, int out_size) {
    const float* x  = (const float*)d_in[0];
    const int*   ei = (const int*)d_in[1];
    const float* W1 = (const float*)d_in[2];
    const float* b1 = (const float*)d_in[3];
    const float* W2 = (const float*)d_in[4];
    const float* b2 = (const float*)d_in[5];
    float* z = (float*)d_out;

    const int4* src4 = (const int4*)ei;
    const int4* dst4 = (const int4*)(ei + N_EDGES);

    // zero cursors via async memset (graph-capturable, no alloc)
    void* cur_ptr = nullptr;
    cudaGetSymbolAddress(&cur_ptr, g_cursor);
    cudaMemsetAsync(cur_ptr, 0, N_NODES * sizeof(int));

    k_bin   <<<BIN_NB + 1, 256>>>(src4, dst4, W1, b1, W2);
    k_fuse  <<<FUSE_NB, FUSE_BS>>>(x);

    // 4 nodes/warp: 25000 warps = 3125 blocks of 256 threads (exact)
    k_agg<0><<<N_NODES / 32, 256>>>(z, b2);
    k_agg<1><<<N_NODES / 32, 256>>>(z, b2);
}